// round 2
// baseline (speedup 1.0000x reference)
#include <cuda_runtime.h>
#include <cstdint>

#define HID   512
#define NSTEP 8192          // BS*T
#define NC    128
#define NT    256           // 8 warps: (dir 0/1) x (4 hidden per CTA per dir)

// Published hidden state: [parity][dir*HID+e], packed (tag<<32)|f32bits
__device__ unsigned long long g_hbuf[2][2 * HID];

// ---------------------------------------------------------------------------
__device__ __forceinline__ void fma2(unsigned long long& d,
                                     unsigned long long a, unsigned long long b) {
    asm volatile("fma.rn.f32x2 %0, %1, %2, %0;" : "+l"(d) : "l"(a), "l"(b));
}
__device__ __forceinline__ void st_rel(unsigned long long* p, unsigned long long v) {
    asm volatile("st.global.relaxed.gpu.u64 [%0], %1;" :: "l"(p), "l"(v) : "memory");
}
__device__ __forceinline__ unsigned long long ld_rel(const unsigned long long* p) {
    unsigned long long v;
    asm volatile("ld.global.relaxed.gpu.u64 %0, [%1];" : "=l"(v) : "l"(p) : "memory");
    return v;
}
__device__ __forceinline__ float lo32(unsigned long long v) { return __uint_as_float((unsigned)v); }
__device__ __forceinline__ float hi32(unsigned long long v) { return __uint_as_float((unsigned)(v >> 32)); }

// ---------------------------------------------------------------------------
// Single persistent fused kernel: input-projection + recurrent scan.
// 128 CTAs x 256 threads. Warp w: dir = w>>2, hU = w&3, e = cta*4+hU.
// Each warp computes all 4 gates of its (dir,e): 64 packed-f32x2 FMAs/lane/step
// (32 x-part off the critical path, 32 h-part on it), shfl-reduced in-warp.
// Cross-CTA sync: tagged 64-bit publishes, parity double-buffer, spin poll.
// ONE __syncthreads per step.
// ---------------------------------------------------------------------------
__global__ void __launch_bounds__(NT, 1) lstm_fused(
    const float* __restrict__ x,
    const float* __restrict__ h0, const float* __restrict__ c0,
    const float* __restrict__ Wif, const float* __restrict__ Whf, const float* __restrict__ bf,
    const float* __restrict__ Wib, const float* __restrict__ Whb, const float* __restrict__ bb,
    float* __restrict__ out)
{
    __shared__ __align__(16) float sh[2][2 * HID];   // [parity][dir*HID+e]
    __shared__ __align__(16) float xb[2][2][HID];    // [parity][dir][d]

    const int t    = threadIdx.x;
    const int cta  = blockIdx.x;
    const int wid  = t >> 5, lane = t & 31;
    const int dir  = wid >> 2, hU = wid & 3;
    const int e    = cta * 4 + hU;

    const float* __restrict__ Wi = dir ? Wib : Wif;
    const float* __restrict__ Wh = dir ? Whb : Whf;
    const float* __restrict__ bs = dir ? bb  : bf;

    // Register-resident weights: lane owns columns {2*lane + 64j, +1}, j=0..7
    unsigned long long wi[4][8], wh[4][8];
    float bias[4];
    #pragma unroll
    for (int g = 0; g < 4; g++) {
        size_t row = (size_t)(g * HID + e) * HID;
        #pragma unroll
        for (int j = 0; j < 8; j++) {
            wi[g][j] = *(const unsigned long long*)(Wi + row + lane * 2 + j * 64);
            wh[g][j] = *(const unsigned long long*)(Wh + row + lane * 2 + j * 64);
        }
        bias[g] = bs[g * HID + e];
    }

    // lane 0 owns the cell state and publishes h
    float cst = 0.f, hv = 0.f;
    if (lane == 0) {
        hv  = h0[dir * HID + e];
        cst = c0[dir * HID + e];
        st_rel(&g_hbuf[0][dir * HID + e],
               (1ull << 32) | (unsigned long long)__float_as_uint(hv));
    }

    // x staging: threads [0,128) carry the fwd row, [128,256) the bwd row.
    const int xoff = (t < 128) ? t * 4 : (t - 128) * 4;
    const int xdir = (t >= 128);
    {
        int r0 = xdir ? 7 : 0;                       // s=0: fwd row 0, bwd row 0^7
        *(float4*)&xb[0][xdir][xoff] =
            *(const float4*)(x + (size_t)r0 * HID + xoff);
    }
    int r1 = xdir ? (1 ^ 7) : 1;                     // prefetch rows for s=1
    float4 xn = *(const float4*)(x + (size_t)r1 * HID + xoff);
    __syncthreads();

    for (int s = 0; s < NSTEP; s++) {
        const int p = s & 1;

        // ---- x-part (no dependency; overlaps publish propagation) ----
        unsigned long long acc0 = 0, acc1 = 0, acc2 = 0, acc3 = 0;
        #pragma unroll
        for (int j = 0; j < 8; j++) {
            unsigned long long xv =
                *(const unsigned long long*)&xb[p][dir][lane * 2 + j * 64];
            fma2(acc0, wi[0][j], xv);
            fma2(acc1, wi[1][j], xv);
            fma2(acc2, wi[2][j], xv);
            fma2(acc3, wi[3][j], xv);
        }

        // ---- poll full hidden vector (4 slots/thread) into smem ----
        {
            const unsigned want = (unsigned)(s + 1);
            unsigned long long* bp = &g_hbuf[p][t * 4];
            unsigned long long v0 = ld_rel(bp + 0), v1 = ld_rel(bp + 1);
            unsigned long long v2 = ld_rel(bp + 2), v3 = ld_rel(bp + 3);
            while ((unsigned)(v0 >> 32) != want) v0 = ld_rel(bp + 0);
            while ((unsigned)(v1 >> 32) != want) v1 = ld_rel(bp + 1);
            while ((unsigned)(v2 >> 32) != want) v2 = ld_rel(bp + 2);
            while ((unsigned)(v3 >> 32) != want) v3 = ld_rel(bp + 3);
            sh[p][t * 4 + 0] = lo32(v0);
            sh[p][t * 4 + 1] = lo32(v1);
            sh[p][t * 4 + 2] = lo32(v2);
            sh[p][t * 4 + 3] = lo32(v3);
        }

        // ---- stash prefetched x row for step s+1 ----
        *(float4*)&xb[p ^ 1][xdir][xoff] = xn;

        __syncthreads();   // the ONLY barrier per step

        // ---- prefetch x row for step s+2 (full step to complete) ----
        {
            int ns2 = (s + 2 <= NSTEP - 1) ? s + 2 : NSTEP - 1;
            int r = xdir ? (ns2 ^ 7) : ns2;
            xn = *(const float4*)(x + (size_t)r * HID + xoff);
        }

        // ---- h-part (critical path) ----
        #pragma unroll
        for (int j = 0; j < 8; j++) {
            unsigned long long hvv =
                *(const unsigned long long*)&sh[p][dir * HID + lane * 2 + j * 64];
            fma2(acc0, wh[0][j], hvv);
            fma2(acc1, wh[1][j], hvv);
            fma2(acc2, wh[2][j], hvv);
            fma2(acc3, wh[3][j], hvv);
        }

        // ---- in-warp reduction ----
        float z0 = lo32(acc0) + hi32(acc0);
        float z1 = lo32(acc1) + hi32(acc1);
        float z2 = lo32(acc2) + hi32(acc2);
        float z3 = lo32(acc3) + hi32(acc3);
        #pragma unroll
        for (int m = 16; m; m >>= 1) {
            z0 += __shfl_xor_sync(0xffffffffu, z0, m);
            z1 += __shfl_xor_sync(0xffffffffu, z1, m);
            z2 += __shfl_xor_sync(0xffffffffu, z2, m);
            z3 += __shfl_xor_sync(0xffffffffu, z3, m);
        }

        // ---- gates + state update + publish (lane 0) ----
        if (lane == 0) {
            float zi = z0 + bias[0], zf = z1 + bias[1];
            float zg = z2 + bias[2], zo = z3 + bias[3];
            float ig = 1.f / (1.f + __expf(-zi));
            float fg = 1.f / (1.f + __expf(-zf));
            float gg = tanhf(zg);
            float oo = 1.f / (1.f + __expf(-zo));
            cst = fmaf(fg, cst, ig * gg);
            hv  = oo * tanhf(cst);

            st_rel(&g_hbuf[p ^ 1][dir * HID + e],
                   (((unsigned long long)(unsigned)(s + 2)) << 32) |
                   (unsigned long long)__float_as_uint(hv));

            size_t orow = dir ? (size_t)(s ^ 7) : (size_t)s;   // bwd un-reverses time
            out[orow * (2 * HID) + dir * HID + e] = hv;

            if (s == NSTEP - 1) {
                out[(size_t)NSTEP * 2 * HID + dir * HID + e] = hv;             // h_n
                out[(size_t)NSTEP * 2 * HID + 2 * HID + dir * HID + e] = cst;  // c_n
            }
        }
    }
}

// ---------------------------------------------------------------------------
extern "C" void kernel_launch(void* const* d_in, const int* in_sizes, int n_in,
                              void* d_out, int out_size)
{
    const float* x   = (const float*)d_in[0];
    const float* h0  = (const float*)d_in[1];
    const float* c0  = (const float*)d_in[2];
    const float* Wif = (const float*)d_in[3];
    const float* Whf = (const float*)d_in[4];
    const float* bf  = (const float*)d_in[5];
    const float* Wib = (const float*)d_in[6];
    const float* Whb = (const float*)d_in[7];
    const float* bb  = (const float*)d_in[8];
    float* out = (float*)d_out;

    lstm_fused<<<NC, NT>>>(x, h0, c0, Wif, Whf, bf, Wib, Whb, bb, out);
}

// round 3
// speedup vs baseline: 1.6549x; 1.6549x over previous
#include <cuda_runtime.h>
#include <cstdint>

#define HID   512
#define NSTEP 8192          // BS*T = 1024*8
#define G4H   2048          // 4*HID
#define DIN   512

#define NC           128    // persistent CTAs
#define SCAN_THREADS 512
#define HC           4      // hidden indices per CTA per direction

#define BM 128
#define BN 128
#define BK 16

// Precomputed input-gate contributions, [dir][step][4H] (bias folded in)
__device__ float g_gates[(size_t)2 * NSTEP * G4H];
// Published hidden state: [parity][dir*HID+e], packed (tag<<32)|f32bits
__device__ unsigned long long g_hbuf[2][2 * HID];

// ---------------------------------------------------------------------------
__device__ __forceinline__ void st_rel(unsigned long long* p, unsigned long long v) {
    asm volatile("st.global.relaxed.gpu.u64 [%0], %1;" :: "l"(p), "l"(v) : "memory");
}
__device__ __forceinline__ unsigned long long ld_rel(const unsigned long long* p) {
    unsigned long long v;
    asm volatile("ld.global.relaxed.gpu.u64 %0, [%1];" : "=l"(v) : "l"(p) : "memory");
    return v;
}
__device__ __forceinline__ float fast_sigmoid(float x) {
    return 1.f / (1.f + __expf(-x));
}
__device__ __forceinline__ float fast_tanh(float x) {
    return 2.f / (1.f + __expf(-2.f * x)) - 1.f;
}

// ---------------------------------------------------------------------------
// Kernel 1: gates GEMM (unchanged from R1 — measured good).
// g[dir][s][r] = dot(x_dir[s], W_ih_dir[r]) + b[r];  dir==1 row = s^7 (T=8)
// ---------------------------------------------------------------------------
__global__ __launch_bounds__(256) void gates_gemm(
    const float* __restrict__ x,
    const float* __restrict__ Wif, const float* __restrict__ bf,
    const float* __restrict__ Wib, const float* __restrict__ bb)
{
    const int dir = blockIdx.z;
    const float* __restrict__ W    = dir ? Wib : Wif;
    const float* __restrict__ bias = dir ? bb  : bf;
    float* __restrict__ out = g_gates + (size_t)dir * NSTEP * G4H;

    __shared__ __align__(16) float As[BK][BM + 4];
    __shared__ __align__(16) float Bs[BK][BN + 4];

    const int tid  = threadIdx.x;
    const int row0 = blockIdx.y * BM;
    const int col0 = blockIdx.x * BN;
    const int tx = tid & 15;
    const int ty = tid >> 4;

    float acc[8][8];
    #pragma unroll
    for (int i = 0; i < 8; i++)
        #pragma unroll
        for (int j = 0; j < 8; j++) acc[i][j] = 0.f;

    for (int k0 = 0; k0 < DIN; k0 += BK) {
        #pragma unroll
        for (int l = 0; l < 2; l++) {
            int idx = tid + l * 256;
            int m   = idx >> 2;
            int kq  = (idx & 3) * 4;
            int srow = row0 + m;
            int xrow = dir ? (srow ^ 7) : srow;
            float4 v = *(const float4*)&x[(size_t)xrow * DIN + k0 + kq];
            As[kq + 0][m] = v.x; As[kq + 1][m] = v.y;
            As[kq + 2][m] = v.z; As[kq + 3][m] = v.w;
            float4 w = *(const float4*)&W[(size_t)(col0 + m) * DIN + k0 + kq];
            Bs[kq + 0][m] = w.x; Bs[kq + 1][m] = w.y;
            Bs[kq + 2][m] = w.z; Bs[kq + 3][m] = w.w;
        }
        __syncthreads();
        #pragma unroll
        for (int kk = 0; kk < BK; kk++) {
            float a[8], b[8];
            float4 a0 = *(const float4*)&As[kk][ty * 8];
            float4 a1 = *(const float4*)&As[kk][ty * 8 + 4];
            a[0]=a0.x; a[1]=a0.y; a[2]=a0.z; a[3]=a0.w;
            a[4]=a1.x; a[5]=a1.y; a[6]=a1.z; a[7]=a1.w;
            float4 b0 = *(const float4*)&Bs[kk][tx * 8];
            float4 b1 = *(const float4*)&Bs[kk][tx * 8 + 4];
            b[0]=b0.x; b[1]=b0.y; b[2]=b0.z; b[3]=b0.w;
            b[4]=b1.x; b[5]=b1.y; b[6]=b1.z; b[7]=b1.w;
            #pragma unroll
            for (int i = 0; i < 8; i++)
                #pragma unroll
                for (int j = 0; j < 8; j++)
                    acc[i][j] = fmaf(a[i], b[j], acc[i][j]);
        }
        __syncthreads();
    }

    #pragma unroll
    for (int i = 0; i < 8; i++) {
        size_t srow = row0 + ty * 8 + i;
        #pragma unroll
        for (int j = 0; j < 8; j++) {
            int c = col0 + tx * 8 + j;
            out[srow * G4H + c] = acc[i][j] + bias[c];
        }
    }
}

// ---------------------------------------------------------------------------
// Kernel 2: persistent bidirectional scan, 2 barriers/step.
// 128 CTAs x 512 threads. Matvec role: thread t -> (dir, gate, h-slice),
// 32 FFMA into 4 partials. Reduce+gates role: warps 0..7 own (dir,hU),
// warp-local LDS + shfl reduce, lane 0 applies gates and publishes.
// ---------------------------------------------------------------------------
__global__ void __launch_bounds__(SCAN_THREADS, 1) lstm_scan(
    const float* __restrict__ h0,
    const float* __restrict__ c0,
    const float* __restrict__ Whf,
    const float* __restrict__ Whb,
    float* __restrict__ out)
{
    __shared__ __align__(16) float sh[2][2 * HID];   // [parity][dir*HID + e]
    __shared__ __align__(16) float part[32][68];     // [dir*16+gate*4+hl][64]

    const int t   = threadIdx.x;
    const int cta = blockIdx.x;
    const int wid = t >> 5, lane = t & 31;

    // ---- matvec role ----
    const int mdir = t >> 8;           // 0 fwd / 1 bwd
    const int og   = (t >> 6) & 3;     // gate
    const int hs   = t & 63;           // h slice [hs*8, hs*8+8)
    const float* __restrict__ Wd = mdir ? Whb : Whf;
    float w[4][8];
    #pragma unroll
    for (int q = 0; q < 4; q++) {
        size_t row = (size_t)(og * HID + cta * HC + q) * HID;
        #pragma unroll
        for (int k = 0; k < 8; k++)
            w[q][k] = Wd[row + hs * 8 + k];
    }

    // ---- reduce/gates role (warps 0..7) ----
    const int rdir = wid >> 2;         // valid for wid<8
    const int hU   = wid & 3;
    const int e    = cta * HC + hU;
    const int rg   = lane >> 3;                       // gate this lane reduces
    const int rrow = rdir * 16 + rg * 4 + hU;
    const int rcol = (lane & 7) * 4;
    const size_t gbase = (size_t)rdir * NSTEP * G4H + e;

    float g4[4];                       // current step's input-gate values (lane 0)
    float cst = 0.f, hv = 0.f;
    if (wid < 8 && lane == 0) {
        hv  = h0[rdir * HID + e];
        cst = c0[rdir * HID + e];
        st_rel(&g_hbuf[0][rdir * HID + e],
               (1ull << 32) | (unsigned long long)__float_as_uint(hv));
        #pragma unroll
        for (int g = 0; g < 4; g++)
            g4[g] = __ldg(g_gates + gbase + (size_t)g * HID);   // step 0
    }

    for (int s = 0; s < NSTEP; s++) {
        const int p = s & 1;

        // Phase 1: poll hidden vector (2 slots/thread) with backoff
        {
            const unsigned want = (unsigned)(s + 1);
            const unsigned long long* bp = &g_hbuf[p][t * 2];
            unsigned long long v0 = ld_rel(bp), v1 = ld_rel(bp + 1);
            while ((unsigned)(v0 >> 32) != want) { __nanosleep(40); v0 = ld_rel(bp); }
            while ((unsigned)(v1 >> 32) != want) { __nanosleep(40); v1 = ld_rel(bp + 1); }
            sh[p][t * 2]     = __uint_as_float((unsigned)v0);
            sh[p][t * 2 + 1] = __uint_as_float((unsigned)v1);
        }
        __syncthreads();   // S1

        // Phase 2: register-tiled matvec partials
        {
            float4 ha = *(const float4*)&sh[p][mdir * HID + hs * 8];
            float4 hb = *(const float4*)&sh[p][mdir * HID + hs * 8 + 4];
            float hr[8] = {ha.x, ha.y, ha.z, ha.w, hb.x, hb.y, hb.z, hb.w};
            float a0 = 0.f, a1 = 0.f, a2 = 0.f, a3 = 0.f;
            #pragma unroll
            for (int k = 0; k < 8; k++) {
                float h = hr[k];
                a0 = fmaf(w[0][k], h, a0);
                a1 = fmaf(w[1][k], h, a1);
                a2 = fmaf(w[2][k], h, a2);
                a3 = fmaf(w[3][k], h, a3);
            }
            int prow = (mdir << 4) + (og << 2);
            part[prow + 0][hs] = a0;
            part[prow + 1][hs] = a1;
            part[prow + 2][hs] = a2;
            part[prow + 3][hs] = a3;
        }
        __syncthreads();   // S2

        // Phase 3: warp-local reduce + gates + publish (warps 0..7)
        if (wid < 8) {
            float4 pa = *(const float4*)&part[rrow][rcol];
            float4 pb = *(const float4*)&part[rrow][rcol + 32];
            float sv = ((pa.x + pa.y) + (pa.z + pa.w))
                     + ((pb.x + pb.y) + (pb.z + pb.w));
            sv += __shfl_xor_sync(0xffffffffu, sv, 1);
            sv += __shfl_xor_sync(0xffffffffu, sv, 2);
            sv += __shfl_xor_sync(0xffffffffu, sv, 4);
            // z_g now at lanes 8g; gather to lane 0
            float z0 = __shfl_sync(0xffffffffu, sv, 0);
            float z1 = __shfl_sync(0xffffffffu, sv, 8);
            float z2 = __shfl_sync(0xffffffffu, sv, 16);
            float z3 = __shfl_sync(0xffffffffu, sv, 24);

            if (lane == 0) {
                float zi = z0 + g4[0];
                float zf = z1 + g4[1];
                float zg = z2 + g4[2];
                float zo = z3 + g4[3];
                float ig = fast_sigmoid(zi);
                float fg = fast_sigmoid(zf);
                float gg = fast_tanh(zg);
                float oo = fast_sigmoid(zo);
                cst = fmaf(fg, cst, ig * gg);
                hv  = oo * fast_tanh(cst);

                st_rel(&g_hbuf[p ^ 1][rdir * HID + e],
                       (((unsigned long long)(unsigned)(s + 2)) << 32) |
                       (unsigned long long)__float_as_uint(hv));

                size_t orow = rdir ? (size_t)(s ^ 7) : (size_t)s;
                out[orow * (2 * HID) + rdir * HID + e] = hv;

                if (s == NSTEP - 1) {
                    out[(size_t)NSTEP * 2 * HID + rdir * HID + e] = hv;
                    out[(size_t)NSTEP * 2 * HID + 2 * HID + rdir * HID + e] = cst;
                } else {
                    // prefetch next step's input-gate values (off critical path)
                    size_t nb = gbase + (size_t)(s + 1) * G4H;
                    #pragma unroll
                    for (int g = 0; g < 4; g++)
                        g4[g] = __ldg(g_gates + nb + (size_t)g * HID);
                }
            }
        }
        // next-step S1 protects part[] reuse; sh is parity double-buffered
    }
}

// ---------------------------------------------------------------------------
extern "C" void kernel_launch(void* const* d_in, const int* in_sizes, int n_in,
                              void* d_out, int out_size)
{
    const float* x   = (const float*)d_in[0];
    const float* h0  = (const float*)d_in[1];
    const float* c0  = (const float*)d_in[2];
    const float* Wif = (const float*)d_in[3];
    const float* Whf = (const float*)d_in[4];
    const float* bf  = (const float*)d_in[5];
    const float* Wib = (const float*)d_in[6];
    const float* Whb = (const float*)d_in[7];
    const float* bb  = (const float*)d_in[8];
    float* out = (float*)d_out;

    dim3 ggrid(G4H / BN, NSTEP / BM, 2);
    gates_gemm<<<ggrid, 256>>>(x, Wif, bf, Wib, bb);
    lstm_scan<<<NC, SCAN_THREADS>>>(h0, c0, Whf, Whb, out);
}